// round 5
// baseline (speedup 1.0000x reference)
#include <cuda_runtime.h>
#include <math.h>

#define NIMG 12
#define N 256
#define NA 180

// Scratch (device globals; no allocation allowed)
__device__ float g_sino[NIMG * N * NA];   // [img][n][a]
__device__ float g_Q[NIMG * N * NA];
__device__ float g_K[NIMG * N * NA];
__device__ float g_V[NIMG * N * NA];
__device__ float g_att[NIMG * N * NA];    // [img][n][a]
__device__ float g_filt[NIMG * NA * N];   // [img][a][n] (transposed for backproj)

__device__ __forceinline__ float pix(const float* im, int y, int x) {
    return ((unsigned)y < 256u && (unsigned)x < 256u) ? __ldg(im + (y << 8) + x) : 0.0f;
}

// ---------------------------------------------------------------------------
// K1: Radon transform. block=(angle, img), thread n = detector index.
// sino[n][a] = sum_y bilinear(img; sy, sx) with
//   sx =  c*n + s*y - 128*(c+s-1)
//   sy = -s*n + c*y - 128*(c-s-1)
// ---------------------------------------------------------------------------
__global__ void k_radon(const float* __restrict__ x) {
    int a = blockIdx.x, img = blockIdx.y, n = threadIdx.x;
    float th = (float)((double)a * M_PI / 180.0);
    float c = cosf(th), s = sinf(th);
    const float* im = x + img * N * N;
    float bx = c * (float)n - 128.0f * (c + s - 1.0f);
    float by = -s * (float)n - 128.0f * (c - s - 1.0f);
    float acc = 0.0f;
    for (int y = 0; y < N; y++) {
        float sx = bx + s * (float)y;
        float sy = by + c * (float)y;
        float fx0 = floorf(sx), fy0 = floorf(sy);
        int ix = (int)fx0, iy = (int)fy0;
        float fx = sx - fx0, fy = sy - fy0;
        float p00 = pix(im, iy, ix);
        float p01 = pix(im, iy, ix + 1);
        float p10 = pix(im, iy + 1, ix);
        float p11 = pix(im, iy + 1, ix + 1);
        acc += (1.0f - fy) * ((1.0f - fx) * p00 + fx * p01)
             + fy * ((1.0f - fx) * p10 + fx * p11);
    }
    g_sino[(img * N + n) * NA + a] = acc;
}

// ---------------------------------------------------------------------------
// K2: QKV projections. out[r][j] = sum_k sino[r][k] * W[j][k] + b[j].
// block=(32-row tile, img), 256 threads = 32 rows x 8 col-lanes.
// ---------------------------------------------------------------------------
__global__ void k_qkv(const float* __restrict__ Wq, const float* __restrict__ bq,
                      const float* __restrict__ Wk, const float* __restrict__ bk,
                      const float* __restrict__ Wv, const float* __restrict__ bv) {
    int img = blockIdx.y, r0 = blockIdx.x * 32;
    __shared__ float As[32 * NA];
    const float* src = g_sino + (img * N + r0) * NA;
    for (int i = threadIdx.x; i < 32 * NA; i += 256) As[i] = src[i];
    __syncthreads();

    int r = threadIdx.x >> 3, sub = threadIdx.x & 7;
    const float4* arow = (const float4*)(As + r * NA);  // 180 floats = 45 float4, 16B aligned

    const float* Ws[3] = {Wq, Wk, Wv};
    const float* bs[3] = {bq, bk, bv};
    float* outs[3];
    outs[0] = g_Q; outs[1] = g_K; outs[2] = g_V;

    for (int m = 0; m < 3; m++) {
        const float* W = Ws[m];
        const float* b = bs[m];
        float* out = outs[m] + (img * N + r0 + r) * NA;
        for (int j = sub; j < NA; j += 8) {
            const float4* wrow = (const float4*)(W + j * NA);
            float acc = 0.0f;
            #pragma unroll
            for (int k = 0; k < 45; k++) {
                float4 av = arow[k];
                float4 wv = __ldg(wrow + k);
                acc += av.x * wv.x + av.y * wv.y + av.z * wv.z + av.w * wv.w;
            }
            out[j] = acc + __ldg(b + j);
        }
    }
}

// ---------------------------------------------------------------------------
// K3: softmax attention. block=(16-qrow tile, img), 256 thr = 16 rows x 16 lanes.
// ---------------------------------------------------------------------------
__global__ void k_attn() {
    int img = blockIdx.y, q0 = blockIdx.x * 16;
    __shared__ float Qs[16 * NA];
    __shared__ float Ss[16][256];

    const float* Qg = g_Q + (img * N + q0) * NA;
    for (int i = threadIdx.x; i < 16 * NA; i += 256) Qs[i] = Qg[i];
    __syncthreads();

    int row = threadIdx.x >> 4, sub = threadIdx.x & 15;
    const float4* qrow = (const float4*)(Qs + row * NA);
    const float* Kg = g_K + img * N * NA;
    const float scale = 0.07453559924999299f;  // 1/sqrt(180)

    float loc[16];
    #pragma unroll
    for (int m = 0; m < 16; m++) {
        int kr = sub + 16 * m;
        const float4* krow = (const float4*)(Kg + kr * NA);
        float acc = 0.0f;
        #pragma unroll
        for (int k = 0; k < 45; k++) {
            float4 qv = qrow[k];
            float4 kv = __ldg(krow + k);
            acc += qv.x * kv.x + qv.y * kv.y + qv.z * kv.z + qv.w * kv.w;
        }
        loc[m] = acc * scale;
    }

    // softmax over 256 entries: 16 per thread x 16 lanes (same-warp segment)
    float mx = loc[0];
    #pragma unroll
    for (int m = 1; m < 16; m++) mx = fmaxf(mx, loc[m]);
    #pragma unroll
    for (int o = 8; o > 0; o >>= 1) mx = fmaxf(mx, __shfl_xor_sync(0xffffffffu, mx, o, 16));
    float sum = 0.0f;
    #pragma unroll
    for (int m = 0; m < 16; m++) { loc[m] = expf(loc[m] - mx); sum += loc[m]; }
    #pragma unroll
    for (int o = 8; o > 0; o >>= 1) sum += __shfl_xor_sync(0xffffffffu, sum, o, 16);
    float inv = 1.0f / sum;
    #pragma unroll
    for (int m = 0; m < 16; m++) Ss[row][sub + 16 * m] = loc[m] * inv;
    __syncthreads();

    // att = S @ V : out[row][j], j = sub + 16*m
    const float* Vg = g_V + img * N * NA;
    float acc[12];
    #pragma unroll
    for (int m = 0; m < 12; m++) acc[m] = 0.0f;
    for (int k = 0; k < 256; k++) {
        float sc = Ss[row][k];
        const float* vr = Vg + k * NA + sub;
        #pragma unroll
        for (int m = 0; m < 12; m++) {
            int j = sub + 16 * m;
            if (j < NA) acc[m] += sc * __ldg(vr + 16 * m);
        }
    }
    float* out = g_att + (img * N + q0 + row) * NA;
    #pragma unroll
    for (int m = 0; m < 12; m++) {
        int j = sub + 16 * m;
        if (j < NA) out[j] = acc[m];
    }
}

// ---------------------------------------------------------------------------
// K4: ramp filter as direct sparse convolution.
// filtered[n] = 0.5*att[n] - (2/pi^2) * sum_{odd d} (att[n-d]+att[n+d])/d^2
// (exactly equivalent to the reference's circular FFT filtering with h = 2f)
// block=(angle, img), thread = n. Output transposed: g_filt[img][a][n].
// ---------------------------------------------------------------------------
__global__ void k_filter() {
    int a = blockIdx.x, img = blockIdx.y, n = threadIdx.x;
    __shared__ float col[256];
    __shared__ float wt[128];
    col[n] = g_att[(img * N + n) * NA + a];
    if (n < 128) {
        float d = 2.0f * n + 1.0f;
        wt[n] = -0.20264236728467555f / (d * d);  // -2/pi^2 / d^2
    }
    __syncthreads();
    float acc = 0.5f * col[n];
    #pragma unroll 4
    for (int i = 0; i < 128; i++) {
        int d = 2 * i + 1;
        float w = wt[i];
        int lo = n - d, hi = n + d;
        if (lo >= 0) acc += w * col[lo];
        if (hi < 256) acc += w * col[hi];
    }
    g_filt[(img * NA + a) * N + n] = acc;
}

// ---------------------------------------------------------------------------
// K5: filtered backprojection. block=(row i, img), thread = col j.
// t = (j-128)*cos - (i-128)*sin + 128; linear interp, zero outside [0,255].
// ---------------------------------------------------------------------------
__global__ void k_back(float* __restrict__ out) {
    int i = blockIdx.x, img = blockIdx.y, j = threadIdx.x;
    __shared__ float cs[NA], sn[NA];
    if (threadIdx.x < NA) {
        float th = (float)((double)threadIdx.x * M_PI / 180.0);
        cs[threadIdx.x] = cosf(th);
        sn[threadIdx.x] = sinf(th);
    }
    __syncthreads();

    float xp = (float)(i - 128);
    float yp = (float)(j - 128);
    const float* F = g_filt + img * NA * N;
    float acc = 0.0f;
    for (int a = 0; a < NA; a++) {
        float t = yp * cs[a] - xp * sn[a] + 128.0f;
        if (t >= 0.0f && t <= 255.0f) {
            float fl = floorf(t);
            int i0 = (int)fl;
            float fr = t - fl;
            const float* colp = F + a * N;
            float v0 = __ldg(colp + i0);
            float v1 = __ldg(colp + min(i0 + 1, 255));
            acc += (1.0f - fr) * v0 + fr * v1;
        }
    }
    int r2 = (i - 128) * (i - 128) + (j - 128) * (j - 128);
    out[(img * N + i) * N + j] = (r2 <= 16384) ? acc * 0.008726646259971648f : 0.0f;
}

// ---------------------------------------------------------------------------
extern "C" void kernel_launch(void* const* d_in, const int* in_sizes, int n_in,
                              void* d_out, int out_size) {
    const float* x  = (const float*)d_in[0];
    const float* Wq = (const float*)d_in[1];
    const float* bq = (const float*)d_in[2];
    const float* Wk = (const float*)d_in[3];
    const float* bk = (const float*)d_in[4];
    const float* Wv = (const float*)d_in[5];
    const float* bv = (const float*)d_in[6];
    float* out = (float*)d_out;

    k_radon <<<dim3(NA, NIMG), 256>>>(x);
    k_qkv   <<<dim3(8, NIMG), 256>>>(Wq, bq, Wk, bk, Wv, bv);
    k_attn  <<<dim3(16, NIMG), 256>>>();
    k_filter<<<dim3(NA, NIMG), 256>>>();
    k_back  <<<dim3(256, NIMG), 256>>>(out);
}

// round 7
// speedup vs baseline: 1.2527x; 1.2527x over previous
#include <cuda_runtime.h>
#include <math.h>

#define NIMG 12
#define N 256
#define NA 180
#define P 258   // padded dim (zero border, index = coord+1)

// Scratch (device globals; no allocation allowed)
__device__ float2 g_im2 [NIMG * P * P];   // [img][y+1][x+1] = (p(y,x), p(y,x+1))
__device__ float2 g_im2T[NIMG * P * P];   // [img][x+1][y+1] = (p(y,x), p(y+1,x))
__device__ float  g_sino[NIMG * N * NA];  // [img][n][a]
__device__ float  g_Q[NIMG * N * NA];
__device__ float  g_K[NIMG * N * NA];
__device__ float  g_V[NIMG * N * NA];
__device__ float  g_att[NIMG * N * NA];   // [img][n][a]
__device__ float2 g_filt2[NIMG * NA * N]; // [img][a][n] = (f[n], f[n+1])

__device__ __forceinline__ float pix(const float* im, int y, int x) {
    return ((unsigned)y < 256u && (unsigned)x < 256u) ? __ldg(im + (y << 8) + x) : 0.0f;
}

// ---------------------------------------------------------------------------
// K0: build padded pair images (normal + transposed layouts).
// ---------------------------------------------------------------------------
__global__ void k_prep(const float* __restrict__ x) {
    int r = blockIdx.x, img = blockIdx.y;
    const float* im = x + img * N * N;
    float2* d  = g_im2  + (size_t)img * P * P + (size_t)r * P;
    float2* dt = g_im2T + (size_t)img * P * P + (size_t)r * P;
    for (int c = threadIdx.x; c < P; c += blockDim.x) {
        d[c]  = make_float2(pix(im, r - 1, c - 1), pix(im, r - 1, c));
        dt[c] = make_float2(pix(im, c - 1, r - 1), pix(im, c, r - 1));
    }
}

// ---------------------------------------------------------------------------
// K1: Radon transform. block=(angle, img), thread n = detector index.
// Layout chosen per angle for coalescing; pair loads halve LDG count.
// ---------------------------------------------------------------------------
__global__ void k_radon() {
    int a = blockIdx.x, img = blockIdx.y, n = threadIdx.x;
    float th = (float)((double)a * M_PI / 180.0);
    float c = cosf(th), s = sinf(th);
    float bx = c * (float)n - 128.0f * (c + s - 1.0f);
    float by = -s * (float)n - 128.0f * (c - s - 1.0f);
    float acc = 0.0f;

    if (fabsf(c) >= fabsf(s)) {
        const float2* im2 = g_im2 + (size_t)img * P * P;
        #pragma unroll 4
        for (int y = 0; y < N; y++) {
            float sx = bx + s * (float)y;
            float sy = by + c * (float)y;
            float fx0 = floorf(sx), fy0 = floorf(sy);
            int ix = (int)fx0, iy = (int)fy0;
            float fx = sx - fx0, fy = sy - fy0;
            int r0 = iy + 1, r1 = iy + 2, cx = ix + 1;
            bool cok = (unsigned)cx < (unsigned)P;
            float2 q0 = (cok && (unsigned)r0 < (unsigned)P) ? __ldg(im2 + r0 * P + cx) : make_float2(0.f, 0.f);
            float2 q1 = (cok && (unsigned)r1 < (unsigned)P) ? __ldg(im2 + r1 * P + cx) : make_float2(0.f, 0.f);
            float p00 = q0.x, p01 = q0.y, p10 = q1.x, p11 = q1.y;
            acc += (1.0f - fy) * ((1.0f - fx) * p00 + fx * p01)
                 + fy * ((1.0f - fx) * p10 + fx * p11);
        }
    } else {
        const float2* imT = g_im2T + (size_t)img * P * P;
        #pragma unroll 4
        for (int y = 0; y < N; y++) {
            float sx = bx + s * (float)y;
            float sy = by + c * (float)y;
            float fx0 = floorf(sx), fy0 = floorf(sy);
            int ix = (int)fx0, iy = (int)fy0;
            float fx = sx - fx0, fy = sy - fy0;
            int x0 = ix + 1, x1 = ix + 2, ry = iy + 1;
            bool rok = (unsigned)ry < (unsigned)P;
            float2 q0 = (rok && (unsigned)x0 < (unsigned)P) ? __ldg(imT + x0 * P + ry) : make_float2(0.f, 0.f);
            float2 q1 = (rok && (unsigned)x1 < (unsigned)P) ? __ldg(imT + x1 * P + ry) : make_float2(0.f, 0.f);
            float p00 = q0.x, p10 = q0.y, p01 = q1.x, p11 = q1.y;
            acc += (1.0f - fy) * ((1.0f - fx) * p00 + fx * p01)
                 + fy * ((1.0f - fx) * p10 + fx * p11);
        }
    }
    g_sino[(img * N + n) * NA + a] = acc;
}

// ---------------------------------------------------------------------------
// K2: QKV projections. block=(32-row tile, img), 256 thr = 32 rows x 8 lanes.
// ---------------------------------------------------------------------------
__global__ void k_qkv(const float* __restrict__ Wq, const float* __restrict__ bq,
                      const float* __restrict__ Wk, const float* __restrict__ bk,
                      const float* __restrict__ Wv, const float* __restrict__ bv) {
    int img = blockIdx.y, r0 = blockIdx.x * 32;
    __shared__ float As[32 * NA];
    const float* src = g_sino + (img * N + r0) * NA;
    for (int i = threadIdx.x; i < 32 * NA; i += 256) As[i] = src[i];
    __syncthreads();

    int r = threadIdx.x >> 3, sub = threadIdx.x & 7;
    const float4* arow = (const float4*)(As + r * NA);

    const float* Ws[3] = {Wq, Wk, Wv};
    const float* bs[3] = {bq, bk, bv};
    float* outs[3];
    outs[0] = g_Q; outs[1] = g_K; outs[2] = g_V;

    for (int m = 0; m < 3; m++) {
        const float* W = Ws[m];
        const float* b = bs[m];
        float* out = outs[m] + (img * N + r0 + r) * NA;
        for (int j = sub; j < NA; j += 8) {
            const float4* wrow = (const float4*)(W + j * NA);
            float acc = 0.0f;
            #pragma unroll
            for (int k = 0; k < 45; k++) {
                float4 av = arow[k];
                float4 wv = __ldg(wrow + k);
                acc += av.x * wv.x + av.y * wv.y + av.z * wv.z + av.w * wv.w;
            }
            out[j] = acc + __ldg(b + j);
        }
    }
}

// ---------------------------------------------------------------------------
// K3: softmax attention. block=(16-qrow tile, img), 256 thr = 16 rows x 16 lanes.
// ---------------------------------------------------------------------------
__global__ void k_attn() {
    int img = blockIdx.y, q0 = blockIdx.x * 16;
    __shared__ float Qs[16 * NA];
    __shared__ float Ss[16][256];

    const float* Qg = g_Q + (img * N + q0) * NA;
    for (int i = threadIdx.x; i < 16 * NA; i += 256) Qs[i] = Qg[i];
    __syncthreads();

    int row = threadIdx.x >> 4, sub = threadIdx.x & 15;
    const float4* qrow = (const float4*)(Qs + row * NA);
    const float* Kg = g_K + img * N * NA;
    const float scale = 0.07453559924999299f;  // 1/sqrt(180)

    float loc[16];
    #pragma unroll
    for (int m = 0; m < 16; m++) {
        int kr = sub + 16 * m;
        const float4* krow = (const float4*)(Kg + kr * NA);
        float acc = 0.0f;
        #pragma unroll
        for (int k = 0; k < 45; k++) {
            float4 qv = qrow[k];
            float4 kv = __ldg(krow + k);
            acc += qv.x * kv.x + qv.y * kv.y + qv.z * kv.z + qv.w * kv.w;
        }
        loc[m] = acc * scale;
    }

    float mx = loc[0];
    #pragma unroll
    for (int m = 1; m < 16; m++) mx = fmaxf(mx, loc[m]);
    #pragma unroll
    for (int o = 8; o > 0; o >>= 1) mx = fmaxf(mx, __shfl_xor_sync(0xffffffffu, mx, o, 16));
    float sum = 0.0f;
    #pragma unroll
    for (int m = 0; m < 16; m++) { loc[m] = expf(loc[m] - mx); sum += loc[m]; }
    #pragma unroll
    for (int o = 8; o > 0; o >>= 1) sum += __shfl_xor_sync(0xffffffffu, sum, o, 16);
    float inv = 1.0f / sum;
    #pragma unroll
    for (int m = 0; m < 16; m++) Ss[row][sub + 16 * m] = loc[m] * inv;
    __syncthreads();

    const float* Vg = g_V + img * N * NA;
    float acc[12];
    #pragma unroll
    for (int m = 0; m < 12; m++) acc[m] = 0.0f;
    for (int k = 0; k < 256; k++) {
        float sc = Ss[row][k];
        const float* vr = Vg + k * NA + sub;
        #pragma unroll
        for (int m = 0; m < 12; m++) {
            int j = sub + 16 * m;
            if (j < NA) acc[m] += sc * __ldg(vr + 16 * m);
        }
    }
    float* out = g_att + (img * N + q0 + row) * NA;
    #pragma unroll
    for (int m = 0; m < 12; m++) {
        int j = sub + 16 * m;
        if (j < NA) out[j] = acc[m];
    }
}

// ---------------------------------------------------------------------------
// K4: ramp filter = sparse conv (exactly equal to FFT ramp filtering).
// Column zero-padded by 256 on EACH side (tap reach is 255) -> no predicates.
// Emits float2 pairs (f[n], f[n+1]) for single-load backprojection.
// ---------------------------------------------------------------------------
__global__ void k_filter() {
    int a = blockIdx.x, img = blockIdx.y, n = threadIdx.x;
    __shared__ float col[768];   // [0..255]=0, [256..511]=data, [512..767]=0
    __shared__ float res[256];
    __shared__ float wt[128];
    col[n] = 0.0f;
    col[n + 512] = 0.0f;
    if (n < 128) {
        float d = 2.0f * n + 1.0f;
        wt[n] = -0.20264236728467555f / (d * d);  // -2/pi^2 / d^2
    }
    col[256 + n] = g_att[(img * N + n) * NA + a];
    __syncthreads();
    float acc = 0.5f * col[256 + n];
    #pragma unroll 8
    for (int i = 0; i < 128; i++) {
        int d = 2 * i + 1;
        acc += wt[i] * (col[256 + n - d] + col[256 + n + d]);
    }
    res[n] = acc;
    __syncthreads();
    float2 o;
    o.x = res[n];
    o.y = (n < 255) ? res[n + 1] : 0.0f;  // frac==0 when i0==255 -> .y unused
    g_filt2[(img * NA + a) * N + n] = o;
}

// ---------------------------------------------------------------------------
// K5: filtered backprojection. block=(row i, img), thread = col j.
// Single float2 load per angle gives both interpolation endpoints.
// ---------------------------------------------------------------------------
__global__ void k_back(float* __restrict__ out) {
    int i = blockIdx.x, img = blockIdx.y, j = threadIdx.x;
    __shared__ float cs[NA], sn[NA];
    if (threadIdx.x < NA) {
        float th = (float)((double)threadIdx.x * M_PI / 180.0);
        cs[threadIdx.x] = cosf(th);
        sn[threadIdx.x] = sinf(th);
    }
    __syncthreads();

    float xp = (float)(i - 128);
    float yp = (float)(j - 128);
    const float2* F = g_filt2 + (size_t)img * NA * N;
    float acc = 0.0f;
    #pragma unroll 4
    for (int a = 0; a < NA; a++) {
        float t = yp * cs[a] - xp * sn[a] + 128.0f;
        if (t >= 0.0f && t <= 255.0f) {
            float fl = floorf(t);
            int i0 = (int)fl;
            float fr = t - fl;
            float2 v = __ldg(F + a * N + i0);
            acc += (1.0f - fr) * v.x + fr * v.y;
        }
    }
    int r2 = (i - 128) * (i - 128) + (j - 128) * (j - 128);
    out[(img * N + i) * N + j] = (r2 <= 16384) ? acc * 0.008726646259971648f : 0.0f;
}

// ---------------------------------------------------------------------------
extern "C" void kernel_launch(void* const* d_in, const int* in_sizes, int n_in,
                              void* d_out, int out_size) {
    const float* x  = (const float*)d_in[0];
    const float* Wq = (const float*)d_in[1];
    const float* bq = (const float*)d_in[2];
    const float* Wk = (const float*)d_in[3];
    const float* bk = (const float*)d_in[4];
    const float* Wv = (const float*)d_in[5];
    const float* bv = (const float*)d_in[6];
    float* out = (float*)d_out;

    k_prep  <<<dim3(P, NIMG), 256>>>(x);
    k_radon <<<dim3(NA, NIMG), 256>>>();
    k_qkv   <<<dim3(8, NIMG), 256>>>(Wq, bq, Wk, bk, Wv, bv);
    k_attn  <<<dim3(16, NIMG), 256>>>();
    k_filter<<<dim3(NA, NIMG), 256>>>();
    k_back  <<<dim3(256, NIMG), 256>>>(out);
}

// round 11
// speedup vs baseline: 1.4453x; 1.1537x over previous
#include <cuda_runtime.h>
#include <math.h>

#define NIMG 12
#define N 256
#define NA 180
#define P 258   // padded dim (zero border, index = coord+1)

// Scratch (device globals; no allocation allowed)
__device__ float2 g_im2 [NIMG * P * P];   // [img][y+1][x+1] = (p(y,x), p(y,x+1))
__device__ float2 g_im2T[NIMG * P * P];   // [img][x+1][y+1] = (p(y,x), p(y+1,x))
__device__ float  g_sino[NIMG * N * NA];  // [img][n][a]
__device__ float  g_Q[NIMG * N * NA];
__device__ float  g_K[NIMG * N * NA];
__device__ float  g_V[NIMG * N * NA];
__device__ float  g_att[NIMG * N * NA];   // [img][n][a]
__device__ float2 g_filt2[NIMG * NA * N]; // [img][a][n] = (f[n], f[n+1])

__device__ __forceinline__ float pix(const float* im, int y, int x) {
    return ((unsigned)y < 256u && (unsigned)x < 256u) ? __ldg(im + (y << 8) + x) : 0.0f;
}

// ---------------------------------------------------------------------------
// K0: build padded pair images (normal + transposed layouts).
// ---------------------------------------------------------------------------
__global__ void k_prep(const float* __restrict__ x) {
    int r = blockIdx.x, img = blockIdx.y;
    const float* im = x + img * N * N;
    float2* d  = g_im2  + (size_t)img * P * P + (size_t)r * P;
    float2* dt = g_im2T + (size_t)img * P * P + (size_t)r * P;
    for (int c = threadIdx.x; c < P; c += blockDim.x) {
        d[c]  = make_float2(pix(im, r - 1, c - 1), pix(im, r - 1, c));
        dt[c] = make_float2(pix(im, c - 1, r - 1), pix(im, c, r - 1));
    }
}

// ---------------------------------------------------------------------------
// K1: Radon transform. block=(angle, img), thread n = detector index.
// Layout chosen per angle for coalescing; pair loads halve LDG count.
// ---------------------------------------------------------------------------
__global__ void k_radon() {
    int a = blockIdx.x, img = blockIdx.y, n = threadIdx.x;
    float th = (float)((double)a * M_PI / 180.0);
    float c = cosf(th), s = sinf(th);
    float bx = c * (float)n - 128.0f * (c + s - 1.0f);
    float by = -s * (float)n - 128.0f * (c - s - 1.0f);
    float acc = 0.0f;

    if (fabsf(c) >= fabsf(s)) {
        const float2* im2 = g_im2 + (size_t)img * P * P;
        #pragma unroll 4
        for (int y = 0; y < N; y++) {
            float sx = bx + s * (float)y;
            float sy = by + c * (float)y;
            float fx0 = floorf(sx), fy0 = floorf(sy);
            int ix = (int)fx0, iy = (int)fy0;
            float fx = sx - fx0, fy = sy - fy0;
            int r0 = iy + 1, r1 = iy + 2, cx = ix + 1;
            bool cok = (unsigned)cx < (unsigned)P;
            float2 q0 = (cok && (unsigned)r0 < (unsigned)P) ? __ldg(im2 + r0 * P + cx) : make_float2(0.f, 0.f);
            float2 q1 = (cok && (unsigned)r1 < (unsigned)P) ? __ldg(im2 + r1 * P + cx) : make_float2(0.f, 0.f);
            float p00 = q0.x, p01 = q0.y, p10 = q1.x, p11 = q1.y;
            acc += (1.0f - fy) * ((1.0f - fx) * p00 + fx * p01)
                 + fy * ((1.0f - fx) * p10 + fx * p11);
        }
    } else {
        const float2* imT = g_im2T + (size_t)img * P * P;
        #pragma unroll 4
        for (int y = 0; y < N; y++) {
            float sx = bx + s * (float)y;
            float sy = by + c * (float)y;
            float fx0 = floorf(sx), fy0 = floorf(sy);
            int ix = (int)fx0, iy = (int)fy0;
            float fx = sx - fx0, fy = sy - fy0;
            int x0 = ix + 1, x1 = ix + 2, ry = iy + 1;
            bool rok = (unsigned)ry < (unsigned)P;
            float2 q0 = (rok && (unsigned)x0 < (unsigned)P) ? __ldg(imT + x0 * P + ry) : make_float2(0.f, 0.f);
            float2 q1 = (rok && (unsigned)x1 < (unsigned)P) ? __ldg(imT + x1 * P + ry) : make_float2(0.f, 0.f);
            float p00 = q0.x, p10 = q0.y, p01 = q1.x, p11 = q1.y;
            acc += (1.0f - fy) * ((1.0f - fx) * p00 + fx * p01)
                 + fy * ((1.0f - fx) * p10 + fx * p11);
        }
    }
    g_sino[(img * N + n) * NA + a] = acc;
}

// ---------------------------------------------------------------------------
// K2: QKV projections. block=(32-row tile, img), 256 thr = 32 rows x 8 lanes.
// ---------------------------------------------------------------------------
__global__ void k_qkv(const float* __restrict__ Wq, const float* __restrict__ bq,
                      const float* __restrict__ Wk, const float* __restrict__ bk,
                      const float* __restrict__ Wv, const float* __restrict__ bv) {
    int img = blockIdx.y, r0 = blockIdx.x * 32;
    __shared__ float As[32 * NA];
    const float* src = g_sino + (img * N + r0) * NA;
    for (int i = threadIdx.x; i < 32 * NA; i += 256) As[i] = src[i];
    __syncthreads();

    int r = threadIdx.x >> 3, sub = threadIdx.x & 7;
    const float4* arow = (const float4*)(As + r * NA);

    const float* Ws[3] = {Wq, Wk, Wv};
    const float* bs[3] = {bq, bk, bv};
    float* outs[3];
    outs[0] = g_Q; outs[1] = g_K; outs[2] = g_V;

    for (int m = 0; m < 3; m++) {
        const float* W = Ws[m];
        const float* b = bs[m];
        float* out = outs[m] + (img * N + r0 + r) * NA;
        for (int j = sub; j < NA; j += 8) {
            const float4* wrow = (const float4*)(W + j * NA);
            float acc = 0.0f;
            #pragma unroll
            for (int k = 0; k < 45; k++) {
                float4 av = arow[k];
                float4 wv = __ldg(wrow + k);
                acc += av.x * wv.x + av.y * wv.y + av.z * wv.z + av.w * wv.w;
            }
            out[j] = acc + __ldg(b + j);
        }
    }
}

// ---------------------------------------------------------------------------
// K3: softmax attention, smem-tiled. block=(16-qrow tile, img), 256 threads.
// thread = (row = t>>4, sub = t&15). K and V stream through one 16x180 smem
// tile; scores live in registers (col = kt*16+sub), softmax via 16-lane shfl,
// then written once to padded smem S for the S@V pass.
// ---------------------------------------------------------------------------
__global__ void k_attn() {
    const int img = blockIdx.y, q0 = blockIdx.x * 16;
    __shared__ float Qs[16 * NA];
    __shared__ float Ts[16 * NA];      // streamed K/V tile
    __shared__ float S[16][257];       // padded: conflict-free rows

    const int t = threadIdx.x;
    const int row = t >> 4, sub = t & 15;

    const float* Qg = g_Q + (img * N + q0) * NA;
    for (int i = t; i < 16 * NA; i += 256) Qs[i] = Qg[i];

    const float* Kg = g_K + img * N * NA;
    const float scale = 0.07453559924999299f;  // 1/sqrt(180)

    const float4* qrow = (const float4*)(Qs + row * NA);
    float loc[16];

    #pragma unroll 1
    for (int kt = 0; kt < 16; kt++) {
        __syncthreads();
        const float* src = Kg + kt * 16 * NA;
        for (int i = t; i < 16 * NA; i += 256) Ts[i] = src[i];
        __syncthreads();
        const float4* krow = (const float4*)(Ts + sub * NA);
        float acc = 0.0f;
        #pragma unroll
        for (int j = 0; j < 45; j++) {
            float4 qv = qrow[j];
            float4 kv = krow[j];
            acc += qv.x * kv.x + qv.y * kv.y + qv.z * kv.z + qv.w * kv.w;
        }
        loc[kt] = acc * scale;   // score for column kt*16+sub
    }

    // softmax across the 256 columns of this row: 16 regs x 16 lanes
    float mx = loc[0];
    #pragma unroll
    for (int m = 1; m < 16; m++) mx = fmaxf(mx, loc[m]);
    #pragma unroll
    for (int o = 8; o > 0; o >>= 1) mx = fmaxf(mx, __shfl_xor_sync(0xffffffffu, mx, o, 16));
    float sum = 0.0f;
    #pragma unroll
    for (int m = 0; m < 16; m++) { loc[m] = expf(loc[m] - mx); sum += loc[m]; }
    #pragma unroll
    for (int o = 8; o > 0; o >>= 1) sum += __shfl_xor_sync(0xffffffffu, sum, o, 16);
    float inv = 1.0f / sum;
    #pragma unroll
    for (int m = 0; m < 16; m++) S[row][m * 16 + sub] = loc[m] * inv;

    // att = S @ V, V streamed through the same tile buffer
    const float* Vg = g_V + img * N * NA;
    float acc[12];
    #pragma unroll
    for (int m = 0; m < 12; m++) acc[m] = 0.0f;

    #pragma unroll 1
    for (int vt = 0; vt < 16; vt++) {
        __syncthreads();
        const float* src = Vg + vt * 16 * NA;
        for (int i = t; i < 16 * NA; i += 256) Ts[i] = src[i];
        __syncthreads();
        #pragma unroll
        for (int k = 0; k < 16; k++) {
            float sc = S[row][vt * 16 + k];
            const float* vr = Ts + k * NA + sub;
            #pragma unroll
            for (int m = 0; m < 12; m++) {
                int j = sub + 16 * m;
                if (j < NA) acc[m] += sc * vr[16 * m];
            }
        }
    }

    float* out = g_att + (img * N + q0 + row) * NA;
    #pragma unroll
    for (int m = 0; m < 12; m++) {
        int j = sub + 16 * m;
        if (j < NA) out[j] = acc[m];
    }
}

// ---------------------------------------------------------------------------
// K4: ramp filter = sparse conv (exactly equal to FFT ramp filtering).
// Column zero-padded by 256 on EACH side (tap reach is 255) -> no predicates.
// Emits float2 pairs (f[n], f[n+1]) for single-load backprojection.
// ---------------------------------------------------------------------------
__global__ void k_filter() {
    int a = blockIdx.x, img = blockIdx.y, n = threadIdx.x;
    __shared__ float col[768];   // [0..255]=0, [256..511]=data, [512..767]=0
    __shared__ float res[256];
    __shared__ float wt[128];
    col[n] = 0.0f;
    col[n + 512] = 0.0f;
    if (n < 128) {
        float d = 2.0f * n + 1.0f;
        wt[n] = -0.20264236728467555f / (d * d);  // -2/pi^2 / d^2
    }
    col[256 + n] = g_att[(img * N + n) * NA + a];
    __syncthreads();
    float acc = 0.5f * col[256 + n];
    #pragma unroll 8
    for (int i = 0; i < 128; i++) {
        int d = 2 * i + 1;
        acc += wt[i] * (col[256 + n - d] + col[256 + n + d]);
    }
    res[n] = acc;
    __syncthreads();
    float2 o;
    o.x = res[n];
    o.y = (n < 255) ? res[n + 1] : 0.0f;  // frac==0 when i0==255 -> .y unused
    g_filt2[(img * NA + a) * N + n] = o;
}

// ---------------------------------------------------------------------------
// K5: filtered backprojection. block=(row i, img), thread = col j.
// Single float2 load per angle gives both interpolation endpoints.
// ---------------------------------------------------------------------------
__global__ void k_back(float* __restrict__ out) {
    int i = blockIdx.x, img = blockIdx.y, j = threadIdx.x;
    __shared__ float cs[NA], sn[NA];
    if (threadIdx.x < NA) {
        float th = (float)((double)threadIdx.x * M_PI / 180.0);
        cs[threadIdx.x] = cosf(th);
        sn[threadIdx.x] = sinf(th);
    }
    __syncthreads();

    float xp = (float)(i - 128);
    float yp = (float)(j - 128);
    const float2* F = g_filt2 + (size_t)img * NA * N;
    float acc = 0.0f;
    #pragma unroll 4
    for (int a = 0; a < NA; a++) {
        float t = yp * cs[a] - xp * sn[a] + 128.0f;
        if (t >= 0.0f && t <= 255.0f) {
            float fl = floorf(t);
            int i0 = (int)fl;
            float fr = t - fl;
            float2 v = __ldg(F + a * N + i0);
            acc += (1.0f - fr) * v.x + fr * v.y;
        }
    }
    int r2 = (i - 128) * (i - 128) + (j - 128) * (j - 128);
    out[(img * N + i) * N + j] = (r2 <= 16384) ? acc * 0.008726646259971648f : 0.0f;
}

// ---------------------------------------------------------------------------
extern "C" void kernel_launch(void* const* d_in, const int* in_sizes, int n_in,
                              void* d_out, int out_size) {
    const float* x  = (const float*)d_in[0];
    const float* Wq = (const float*)d_in[1];
    const float* bq = (const float*)d_in[2];
    const float* Wk = (const float*)d_in[3];
    const float* bk = (const float*)d_in[4];
    const float* Wv = (const float*)d_in[5];
    const float* bv = (const float*)d_in[6];
    float* out = (float*)d_out;

    k_prep  <<<dim3(P, NIMG), 256>>>(x);
    k_radon <<<dim3(NA, NIMG), 256>>>();
    k_qkv   <<<dim3(8, NIMG), 256>>>(Wq, bq, Wk, bk, Wv, bv);
    k_attn  <<<dim3(16, NIMG), 256>>>();
    k_filter<<<dim3(NA, NIMG), 256>>>();
    k_back  <<<dim3(256, NIMG), 256>>>(out);
}

// round 12
// speedup vs baseline: 2.0178x; 1.3961x over previous
#include <cuda_runtime.h>
#include <math.h>

#define NIMG 12
#define N 256
#define NA 180
#define P 258   // padded dim (zero border, index = coord+1)

// Scratch (device globals; no allocation allowed)
__device__ float4 g_quad [NIMG * P * P];  // [img][y+1][x+1] = (p00,p01,p10,p11) at (y,x)
__device__ float4 g_quadT[NIMG * P * P];  // [img][x+1][y+1] = (p00,p10,p01,p11) at (y,x)
__device__ float  g_sino[NIMG * N * NA];  // [img][n][a]
__device__ float  g_Q[NIMG * N * NA];
__device__ float  g_K[NIMG * N * NA];
__device__ float  g_V[NIMG * N * NA];
__device__ float  g_att[NIMG * N * NA];   // [img][n][a]
__device__ float2 g_filt2[NIMG * NA * N]; // [img][a][n] = (f[n], f[n+1])

__device__ __forceinline__ float pix(const float* im, int y, int x) {
    return ((unsigned)y < 256u && (unsigned)x < 256u) ? __ldg(im + (y << 8) + x) : 0.0f;
}

// ---------------------------------------------------------------------------
// K0: build padded quad images (normal + transposed layouts).
// g_quad[r][c]  holds the 2x2 neighborhood anchored at (y=r-1, x=c-1).
// g_quadT[r][c] holds it anchored at (y=c-1, x=r-1), components reordered so
// that radon's transposed path reads (p00,p10,p01,p11).
// ---------------------------------------------------------------------------
__global__ void k_prep(const float* __restrict__ x) {
    int r = blockIdx.x, img = blockIdx.y;
    const float* im = x + img * N * N;
    float4* d  = g_quad  + (size_t)img * P * P + (size_t)r * P;
    float4* dt = g_quadT + (size_t)img * P * P + (size_t)r * P;
    for (int c = threadIdx.x; c < P; c += blockDim.x) {
        int y = r - 1, xx = c - 1;
        d[c]  = make_float4(pix(im, y, xx),     pix(im, y, xx + 1),
                            pix(im, y + 1, xx), pix(im, y + 1, xx + 1));
        // anchored at (y=c-1, x=r-1): (p00, p10, p01, p11)
        int ty = c - 1, tx = r - 1;
        dt[c] = make_float4(pix(im, ty, tx),     pix(im, ty + 1, tx),
                            pix(im, ty, tx + 1), pix(im, ty + 1, tx + 1));
    }
}

// ---------------------------------------------------------------------------
// K1: Radon transform. block=(angle, img), thread n = detector index.
// One predicated LDG.128 per bilinear sample; layout chosen per angle.
// ---------------------------------------------------------------------------
__global__ void k_radon() {
    int a = blockIdx.x, img = blockIdx.y, n = threadIdx.x;
    float th = (float)((double)a * M_PI / 180.0);
    float c = cosf(th), s = sinf(th);
    float bx = c * (float)n - 128.0f * (c + s - 1.0f);
    float by = -s * (float)n - 128.0f * (c - s - 1.0f);
    float acc = 0.0f;
    const float4 Z = make_float4(0.f, 0.f, 0.f, 0.f);

    if (fabsf(c) >= fabsf(s)) {
        const float4* im4 = g_quad + (size_t)img * P * P;
        #pragma unroll 4
        for (int y = 0; y < N; y++) {
            float sx = bx + s * (float)y;
            float sy = by + c * (float)y;
            float fx0 = floorf(sx), fy0 = floorf(sy);
            int ix = (int)fx0, iy = (int)fy0;
            float fx = sx - fx0, fy = sy - fy0;
            int rr = iy + 1, cc = ix + 1;
            bool ok = ((unsigned)rr < (unsigned)P) & ((unsigned)cc < (unsigned)P);
            float4 q = ok ? __ldg(im4 + rr * P + cc) : Z;
            acc += (1.0f - fy) * ((1.0f - fx) * q.x + fx * q.y)
                 + fy * ((1.0f - fx) * q.z + fx * q.w);
        }
    } else {
        const float4* imT = g_quadT + (size_t)img * P * P;
        #pragma unroll 4
        for (int y = 0; y < N; y++) {
            float sx = bx + s * (float)y;
            float sy = by + c * (float)y;
            float fx0 = floorf(sx), fy0 = floorf(sy);
            int ix = (int)fx0, iy = (int)fy0;
            float fx = sx - fx0, fy = sy - fy0;
            int rr = ix + 1, cc = iy + 1;   // transposed indexing: [x+1][y+1]
            bool ok = ((unsigned)rr < (unsigned)P) & ((unsigned)cc < (unsigned)P);
            float4 q = ok ? __ldg(imT + rr * P + cc) : Z;
            // q = (p00, p10, p01, p11)
            acc += (1.0f - fy) * ((1.0f - fx) * q.x + fx * q.z)
                 + fy * ((1.0f - fx) * q.y + fx * q.w);
        }
    }
    g_sino[(img * N + n) * NA + a] = acc;
}

// ---------------------------------------------------------------------------
// K2: QKV projections. block=(32-row tile, img, matrix), 256 thr.
// ---------------------------------------------------------------------------
__global__ void k_qkv(const float* __restrict__ Wq, const float* __restrict__ bq,
                      const float* __restrict__ Wk, const float* __restrict__ bk,
                      const float* __restrict__ Wv, const float* __restrict__ bv) {
    int img = blockIdx.y, r0 = blockIdx.x * 32, m = blockIdx.z;
    __shared__ float As[32 * NA];
    const float* src = g_sino + (img * N + r0) * NA;
    for (int i = threadIdx.x; i < 32 * NA; i += 256) As[i] = src[i];
    __syncthreads();

    int r = threadIdx.x >> 3, sub = threadIdx.x & 7;
    const float4* arow = (const float4*)(As + r * NA);

    const float* W = (m == 0) ? Wq : (m == 1) ? Wk : Wv;
    const float* b = (m == 0) ? bq : (m == 1) ? bk : bv;
    float* outbase = (m == 0) ? g_Q : (m == 1) ? g_K : g_V;
    float* out = outbase + (img * N + r0 + r) * NA;

    for (int j = sub; j < NA; j += 8) {
        const float4* wrow = (const float4*)(W + j * NA);
        float acc = 0.0f;
        #pragma unroll
        for (int k = 0; k < 45; k++) {
            float4 av = arow[k];
            float4 wv = __ldg(wrow + k);
            acc += av.x * wv.x + av.y * wv.y + av.z * wv.z + av.w * wv.w;
        }
        out[j] = acc + __ldg(b + j);
    }
}

// ---------------------------------------------------------------------------
// K3: softmax attention. block=(8-qrow tile, img), 256 threads.
// warp w = q-row w; lane = score column within a 32-wide K tile.
// K and V stream through one 32x180 smem tile.
// ---------------------------------------------------------------------------
__global__ void k_attn() {
    const int img = blockIdx.y, q0 = blockIdx.x * 8;
    __shared__ float Qs[8 * NA];
    __shared__ float Ts[32 * NA];      // streamed K/V tile (23KB)
    __shared__ float S[8][257];        // padded scores

    const int t = threadIdx.x;
    const int row = t >> 5, lane = t & 31;

    const float* Qg = g_Q + (img * N + q0) * NA;
    for (int i = t; i < 8 * NA; i += 256) Qs[i] = Qg[i];

    const float* Kg = g_K + img * N * NA;
    const float scale = 0.07453559924999299f;  // 1/sqrt(180)

    const float4* qrow = (const float4*)(Qs + row * NA);
    float loc[8];

    #pragma unroll 1
    for (int kt = 0; kt < 8; kt++) {
        __syncthreads();
        const float* src = Kg + kt * 32 * NA;
        for (int i = t; i < 32 * NA; i += 256) Ts[i] = src[i];
        __syncthreads();
        const float4* krow = (const float4*)(Ts + lane * NA);
        float acc = 0.0f;
        #pragma unroll
        for (int j = 0; j < 45; j++) {
            float4 qv = qrow[j];
            float4 kv = krow[j];
            acc += qv.x * kv.x + qv.y * kv.y + qv.z * kv.z + qv.w * kv.w;
        }
        loc[kt] = acc * scale;   // score for column kt*32+lane
    }

    // softmax across 256 columns of this q-row: 8 regs x 32 lanes (full warp)
    float mx = loc[0];
    #pragma unroll
    for (int m = 1; m < 8; m++) mx = fmaxf(mx, loc[m]);
    #pragma unroll
    for (int o = 16; o > 0; o >>= 1) mx = fmaxf(mx, __shfl_xor_sync(0xffffffffu, mx, o));
    float sum = 0.0f;
    #pragma unroll
    for (int m = 0; m < 8; m++) { loc[m] = expf(loc[m] - mx); sum += loc[m]; }
    #pragma unroll
    for (int o = 16; o > 0; o >>= 1) sum += __shfl_xor_sync(0xffffffffu, sum, o);
    float inv = 1.0f / sum;
    #pragma unroll
    for (int m = 0; m < 8; m++) S[row][m * 32 + lane] = loc[m] * inv;

    // att = S @ V, V streamed through the same tile buffer, k ascending
    const float* Vg = g_V + img * N * NA;
    float acc[6];
    #pragma unroll
    for (int m = 0; m < 6; m++) acc[m] = 0.0f;

    #pragma unroll 1
    for (int vt = 0; vt < 8; vt++) {
        __syncthreads();
        const float* src = Vg + vt * 32 * NA;
        for (int i = t; i < 32 * NA; i += 256) Ts[i] = src[i];
        __syncthreads();
        #pragma unroll
        for (int k = 0; k < 32; k++) {
            float sc = S[row][vt * 32 + k];
            const float* vr = Ts + k * NA + lane;
            #pragma unroll
            for (int m = 0; m < 6; m++) {
                int j = lane + 32 * m;
                if (j < NA) acc[m] += sc * vr[32 * m];
            }
        }
    }

    float* out = g_att + (img * N + q0 + row) * NA;
    #pragma unroll
    for (int m = 0; m < 6; m++) {
        int j = lane + 32 * m;
        if (j < NA) out[j] = acc[m];
    }
}

// ---------------------------------------------------------------------------
// K4: ramp filter = sparse conv (exactly equal to FFT ramp filtering).
// Column zero-padded by 256 on EACH side (tap reach is 255) -> no predicates.
// Emits float2 pairs (f[n], f[n+1]) for single-load backprojection.
// ---------------------------------------------------------------------------
__global__ void k_filter() {
    int a = blockIdx.x, img = blockIdx.y, n = threadIdx.x;
    __shared__ float col[768];   // [0..255]=0, [256..511]=data, [512..767]=0
    __shared__ float res[256];
    __shared__ float wt[128];
    col[n] = 0.0f;
    col[n + 512] = 0.0f;
    if (n < 128) {
        float d = 2.0f * n + 1.0f;
        wt[n] = -0.20264236728467555f / (d * d);  // -2/pi^2 / d^2
    }
    col[256 + n] = g_att[(img * N + n) * NA + a];
    __syncthreads();
    float acc = 0.5f * col[256 + n];
    #pragma unroll 8
    for (int i = 0; i < 128; i++) {
        int d = 2 * i + 1;
        acc += wt[i] * (col[256 + n - d] + col[256 + n + d]);
    }
    res[n] = acc;
    __syncthreads();
    float2 o;
    o.x = res[n];
    o.y = (n < 255) ? res[n + 1] : 0.0f;  // frac==0 when i0==255 -> .y unused
    g_filt2[(img * NA + a) * N + n] = o;
}

// ---------------------------------------------------------------------------
// K5: filtered backprojection. block=(row i, img), thread = col j.
// Single float2 load per angle gives both interpolation endpoints.
// ---------------------------------------------------------------------------
__global__ void k_back(float* __restrict__ out) {
    int i = blockIdx.x, img = blockIdx.y, j = threadIdx.x;
    __shared__ float cs[NA], sn[NA];
    if (threadIdx.x < NA) {
        float th = (float)((double)threadIdx.x * M_PI / 180.0);
        cs[threadIdx.x] = cosf(th);
        sn[threadIdx.x] = sinf(th);
    }
    __syncthreads();

    float xp = (float)(i - 128);
    float yp = (float)(j - 128);
    const float2* F = g_filt2 + (size_t)img * NA * N;
    float acc = 0.0f;
    #pragma unroll 4
    for (int a = 0; a < NA; a++) {
        float t = yp * cs[a] - xp * sn[a] + 128.0f;
        if (t >= 0.0f && t <= 255.0f) {
            float fl = floorf(t);
            int i0 = (int)fl;
            float fr = t - fl;
            float2 v = __ldg(F + a * N + i0);
            acc += (1.0f - fr) * v.x + fr * v.y;
        }
    }
    int r2 = (i - 128) * (i - 128) + (j - 128) * (j - 128);
    out[(img * N + i) * N + j] = (r2 <= 16384) ? acc * 0.008726646259971648f : 0.0f;
}

// ---------------------------------------------------------------------------
extern "C" void kernel_launch(void* const* d_in, const int* in_sizes, int n_in,
                              void* d_out, int out_size) {
    const float* x  = (const float*)d_in[0];
    const float* Wq = (const float*)d_in[1];
    const float* bq = (const float*)d_in[2];
    const float* Wk = (const float*)d_in[3];
    const float* bk = (const float*)d_in[4];
    const float* Wv = (const float*)d_in[5];
    const float* bv = (const float*)d_in[6];
    float* out = (float*)d_out;

    k_prep  <<<dim3(P, NIMG), 256>>>(x);
    k_radon <<<dim3(NA, NIMG), 256>>>();
    k_qkv   <<<dim3(8, NIMG, 3), 256>>>(Wq, bq, Wk, bk, Wv, bv);
    k_attn  <<<dim3(32, NIMG), 256>>>();
    k_filter<<<dim3(NA, NIMG), 256>>>();
    k_back  <<<dim3(256, NIMG), 256>>>(out);
}